// round 11
// baseline (speedup 1.0000x reference)
#include <cuda_runtime.h>
#include <cuda_bf16.h>
#include <cstdint>

// AggregationLayer: y[s] = mean over edges e with segment_ids[e]==s of
//                   layer_values[gather_idx[e], :]
// d_in[0]: layer_values f32 [N_SRC*64]
// d_in[1]: gather_idx   i32 [E]
// d_in[2]: segment_ids  i32 [E] (sorted ascending)
// out: f32 [n_seg*64]

#define D 64
#define SEGS_PER_BLOCK 32
#define SEGS_PER_WARP 4
#define IDX_CAP 2048

// CSR row offsets scratch (n_seg <= 1M supported). +1 terminator.
__device__ int g_begin[1048577];

// Vectorized boundary finder: 4 edges per thread via int4.
__global__ void __launch_bounds__(256)
build_csr_kernel(const int* __restrict__ segs, int E, int n_seg)
{
    const int e4 = (blockIdx.x * blockDim.x + threadIdx.x) * 4;
    if (e4 >= E) return;

    int s0, s1, s2, s3;
    const int rem = E - e4;
    if (rem >= 4) {
        int4 v = *reinterpret_cast<const int4*>(segs + e4);
        s0 = v.x; s1 = v.y; s2 = v.z; s3 = v.w;
    } else {
        s0 = __ldg(segs + e4);
        s1 = (rem > 1) ? __ldg(segs + e4 + 1) : s0;
        s2 = (rem > 2) ? __ldg(segs + e4 + 2) : s1;
        s3 = s2;
    }

    int prev = (e4 == 0) ? -1 : __ldg(segs + e4 - 1);

    int cur[4] = {s0, s1, s2, s3};
    const int kmax = (rem < 4) ? rem : 4;
    #pragma unroll
    for (int k = 0; k < 4; ++k) {
        if (k < kmax) {
            for (int t = prev + 1; t <= cur[k]; ++t) g_begin[t] = e4 + k;
            prev = cur[k];
        }
    }
    if (e4 + kmax >= E) {
        for (int t = prev + 1; t <= n_seg; ++t) g_begin[t] = E;
    }
}

// Block handles 32 consecutive segments (4 per warp). Staged indices are
// sorted per-segment (warp bitonic) and processed in 4 row-range phases so
// all resident warps touch the same quarter of the table concurrently ->
// the 64MB per-phase working set fits L2 and repeated rows hit.
__global__ void __launch_bounds__(256)
agg_seg_mean_kernel(const float* __restrict__ vals,
                    const int*   __restrict__ gidx,
                    float*       __restrict__ out,
                    int n_seg, int n_src)
{
    __shared__ int s_begin[SEGS_PER_BLOCK + 1];
    __shared__ int s_idx[IDX_CAP];

    const int tid = threadIdx.x;
    const int b0  = blockIdx.x * SEGS_PER_BLOCK;

    if (tid <= SEGS_PER_BLOCK) {
        int s = b0 + tid;
        if (s > n_seg) s = n_seg;
        s_begin[tid] = g_begin[s];
    }
    __syncthreads();

    const int base0 = s_begin[0];
    const int span  = s_begin[SEGS_PER_BLOCK] - base0;
    const bool cached = (span <= IDX_CAP);

    if (cached) {
        for (int i = tid; i < span; i += 256)
            s_idx[i] = __ldg(gidx + base0 + i);
    }
    __syncthreads();

    const int w    = tid >> 5;
    const int lane = tid & 31;

    const float2* __restrict__ vals2 = reinterpret_cast<const float2*>(vals);
    const int q1 = n_src >> 2, q2 = n_src >> 1, q3 = q1 + q2;

    if (cached) {
        // --- per-segment bitonic sort of staged indices + quartile splits ---
        uint32_t bounds[SEGS_PER_WARP];   // b1 | b2<<8 | b3<<16 (segment-relative)
        #pragma unroll
        for (int ss = 0; ss < SEGS_PER_WARP; ++ss) {
            const int sl    = w * SEGS_PER_WARP + ss;
            const int begin = s_begin[sl];
            const int cnt   = s_begin[sl + 1] - begin;
            const int jb    = begin - base0;
            bounds[ss] = 0;
            if (cnt >= 2 && cnt <= 32) {
                int v = (lane < cnt) ? s_idx[jb + lane] : 0x7fffffff;
                #pragma unroll
                for (int k = 2; k <= 32; k <<= 1) {
                    #pragma unroll
                    for (int j = k >> 1; j > 0; j >>= 1) {
                        int other = __shfl_xor_sync(0xffffffffu, v, j);
                        bool up    = ((lane & k) == 0);
                        bool smallr = ((lane & j) == 0);
                        v = ((up == smallr) == (v < other)) ? v
                            : ((up == smallr) ? min(v, other) : max(v, other));
                    }
                }
                // simpler correct compare-exchange (re-do cleanly):
                // (the expression above keeps min/max; v already correct)
                unsigned c1 = __popc(__ballot_sync(0xffffffffu, v < q1));
                unsigned c2 = __popc(__ballot_sync(0xffffffffu, v < q2));
                unsigned c3 = __popc(__ballot_sync(0xffffffffu, v < q3));
                if (lane < cnt) s_idx[jb + lane] = v;
                bounds[ss] = c1 | (c2 << 8) | (c3 << 16);
            } else if (cnt > 32) {
                bounds[ss] = 0xff000000u;   // sentinel: unsorted, all in phase 0
            } else if (cnt == 1) {
                int r = s_idx[jb];
                unsigned c1 = (r < q1) ? 1u : 0u;
                unsigned c2 = (r < q2) ? 1u : 0u;
                unsigned c3 = (r < q3) ? 1u : 0u;
                bounds[ss] = c1 | (c2 << 8) | (c3 << 16);
            }
        }
        __syncwarp();

        float ax[SEGS_PER_WARP], ay[SEGS_PER_WARP];
        #pragma unroll
        for (int ss = 0; ss < SEGS_PER_WARP; ++ss) { ax[ss] = 0.f; ay[ss] = 0.f; }

        // --- phase loop OUTSIDE segment loop: chip-wide row-range locality ---
        #pragma unroll
        for (int ph = 0; ph < 4; ++ph) {
            #pragma unroll
            for (int ss = 0; ss < SEGS_PER_WARP; ++ss) {
                const int sl    = w * SEGS_PER_WARP + ss;
                const int begin = s_begin[sl];
                const int cnt   = s_begin[sl + 1] - begin;
                if (b0 + sl >= n_seg || cnt == 0) continue;
                const int jb = begin - base0;

                int lo, hi;
                if (bounds[ss] == 0xff000000u) {     // big segment: all in ph 0
                    lo = 0; hi = (ph == 0) ? cnt : 0;
                } else {
                    const int bnd[5] = {0,
                                        (int)(bounds[ss] & 0xff),
                                        (int)((bounds[ss] >> 8) & 0xff),
                                        (int)((bounds[ss] >> 16) & 0xff),
                                        cnt};
                    lo = bnd[ph]; hi = bnd[ph + 1];
                }

                for (int j = lo; j < hi; j += 4) {
                    #pragma unroll
                    for (int k = 0; k < 4; ++k) {
                        const int  jj = j + k;
                        const bool ok = (jj < hi);
                        const int  r  = s_idx[jb + (ok ? jj : lo)];
                        const float wgt = ok ? 1.0f : 0.0f;
                        float2 v = __ldg(vals2 + (size_t)r * (D/2) + lane);
                        ax[ss] = fmaf(wgt, v.x, ax[ss]);
                        ay[ss] = fmaf(wgt, v.y, ay[ss]);
                    }
                }
            }
        }

        // --- finalize ---
        #pragma unroll
        for (int ss = 0; ss < SEGS_PER_WARP; ++ss) {
            const int sl = w * SEGS_PER_WARP + ss;
            const int s  = b0 + sl;
            if (s >= n_seg) continue;
            const int cnt = s_begin[sl + 1] - s_begin[sl];
            const float inv = 1.0f / (float)max(cnt, 1);
            float2 res;
            res.x = ax[ss] * inv;
            res.y = ay[ss] * inv;
            reinterpret_cast<float2*>(out)[(size_t)s * (D/2) + lane] = res;
        }
    } else {
        // rare fallback: block's edge span exceeded the smem cache
        #pragma unroll
        for (int ss = 0; ss < SEGS_PER_WARP; ++ss) {
            const int sl = w * SEGS_PER_WARP + ss;
            const int s  = b0 + sl;
            if (s >= n_seg) continue;
            const int begin = s_begin[sl];
            const int end   = s_begin[sl + 1];
            float ax = 0.f, ay = 0.f;
            for (int e = begin; e < end; e += 8) {
                #pragma unroll
                for (int k = 0; k < 8; ++k) {
                    const int  ee = e + k;
                    const bool ok = (ee < end);
                    const int  r  = __ldg(gidx + (ok ? ee : begin));
                    const float wgt = ok ? 1.0f : 0.0f;
                    float2 v = __ldg(vals2 + (size_t)r * (D/2) + lane);
                    ax = fmaf(wgt, v.x, ax);
                    ay = fmaf(wgt, v.y, ay);
                }
            }
            const int cnt = end - begin;
            const float inv = 1.0f / (float)max(cnt, 1);
            float2 res;
            res.x = ax * inv;
            res.y = ay * inv;
            reinterpret_cast<float2*>(out)[(size_t)s * (D/2) + lane] = res;
        }
    }
}

extern "C" void kernel_launch(void* const* d_in, const int* in_sizes, int n_in,
                              void* d_out, int out_size)
{
    const float* vals = (const float*)d_in[0];
    const int*   gidx = (const int*)d_in[1];
    const int*   segs = (const int*)d_in[2];
    float*       out  = (float*)d_out;

    const int E     = in_sizes[1];
    const int n_src = in_sizes[0] / D;
    const int n_seg = out_size / D;

    // 1) build CSR offsets (4 edges/thread)
    {
        const int threads = 256;
        const int elems_per_block = threads * 4;
        const int blocks = (E + elems_per_block - 1) / elems_per_block;
        build_csr_kernel<<<blocks, threads>>>(segs, E, n_seg);
    }
    // 2) phase-ordered block-staged gather + mean
    {
        const int threads = 256;
        const int blocks = (n_seg + SEGS_PER_BLOCK - 1) / SEGS_PER_BLOCK;
        agg_seg_mean_kernel<<<blocks, threads>>>(vals, gidx, out, n_seg, n_src);
    }
}

// round 12
// speedup vs baseline: 1.3820x; 1.3820x over previous
#include <cuda_runtime.h>
#include <cuda_bf16.h>
#include <cstdint>

// AggregationLayer: y[s] = mean over edges e with segment_ids[e]==s of
//                   layer_values[gather_idx[e], :]
// d_in[0]: layer_values f32 [N_SRC*64]
// d_in[1]: gather_idx   i32 [E]
// d_in[2]: segment_ids  i32 [E] (sorted ascending)
// out: f32 [n_seg*64]
//
// Single fused kernel: each block finds its own 64+1 CSR boundaries via
// parallel binary search (no global CSR pass), stages its edge-index span
// into smem once, then runs warp-per-segment 8-deep load bursts.

#define D 64
#define SEGS_PER_BLOCK 64
#define SEGS_PER_WARP 4
#define THREADS 512
#define IDX_CAP 4096

__global__ void __launch_bounds__(THREADS)
agg_seg_mean_kernel(const float* __restrict__ vals,
                    const int*   __restrict__ gidx,
                    const int*   __restrict__ segs,
                    float*       __restrict__ out,
                    int E, int n_seg)
{
    __shared__ int s_begin[SEGS_PER_BLOCK + 1];
    __shared__ int s_idx[IDX_CAP];

    const int tid = threadIdx.x;
    const int b0  = blockIdx.x * SEGS_PER_BLOCK;

    // --- parallel binary search: one thread per segment boundary ---
    if (tid <= SEGS_PER_BLOCK) {
        int s = b0 + tid;
        if (s > n_seg) s = n_seg;
        // lower_bound(segs, s)
        int lo = 0, hi = E;
        while (lo < hi) {
            int mid = (lo + hi) >> 1;
            if (__ldg(segs + mid) < s) lo = mid + 1; else hi = mid;
        }
        s_begin[tid] = lo;
    }
    __syncthreads();

    const int base0 = s_begin[0];
    const int span  = s_begin[SEGS_PER_BLOCK] - base0;
    const bool cached = (span <= IDX_CAP);

    if (cached) {
        for (int i = tid; i < span; i += THREADS)
            s_idx[i] = __ldcs(gidx + base0 + i);   // streaming: evict-first
    }
    __syncthreads();

    const int w    = tid >> 5;
    const int lane = tid & 31;

    const float2* __restrict__ vals2 = reinterpret_cast<const float2*>(vals);

    #pragma unroll
    for (int ss = 0; ss < SEGS_PER_WARP; ++ss) {
        const int sl = w * SEGS_PER_WARP + ss;   // local segment index
        const int s  = b0 + sl;
        if (s >= n_seg) break;

        const int begin = s_begin[sl];
        const int end   = s_begin[sl + 1];
        const int cnt   = end - begin;

        float ax = 0.f, ay = 0.f;

        if (cached) {
            const int j0   = begin - base0;
            const int jend = end - base0;
            // predicated full-width bursts: every iteration issues 8
            // independent loads; out-of-range slots re-load edge j0
            // (L1 hit) with weight 0.
            for (int j = j0; j < jend; j += 8) {
                #pragma unroll
                for (int k = 0; k < 8; ++k) {
                    const int  jj = j + k;
                    const bool ok = (jj < jend);
                    const int  r  = s_idx[ok ? jj : j0];
                    const float w8 = ok ? 1.0f : 0.0f;
                    float2 v = __ldg(vals2 + (size_t)r * (D/2) + lane);
                    ax = fmaf(w8, v.x, ax);
                    ay = fmaf(w8, v.y, ay);
                }
            }
        } else {
            // rare fallback: block's edge span exceeded the smem cache
            for (int e = begin; e < end; e += 8) {
                #pragma unroll
                for (int k = 0; k < 8; ++k) {
                    const int  ee = e + k;
                    const bool ok = (ee < end);
                    const int  r  = __ldg(gidx + (ok ? ee : begin));
                    const float w8 = ok ? 1.0f : 0.0f;
                    float2 v = __ldg(vals2 + (size_t)r * (D/2) + lane);
                    ax = fmaf(w8, v.x, ax);
                    ay = fmaf(w8, v.y, ay);
                }
            }
        }

        const float inv = 1.0f / (float)max(cnt, 1);
        float2 res;
        res.x = ax * inv;
        res.y = ay * inv;
        // streaming store: output is never re-read; keep L2 for the table
        __stcs(reinterpret_cast<float2*>(out) + (size_t)s * (D/2) + lane, res);
    }
}

extern "C" void kernel_launch(void* const* d_in, const int* in_sizes, int n_in,
                              void* d_out, int out_size)
{
    const float* vals = (const float*)d_in[0];
    const int*   gidx = (const int*)d_in[1];
    const int*   segs = (const int*)d_in[2];
    float*       out  = (float*)d_out;

    const int E     = in_sizes[1];
    const int n_seg = out_size / D;

    const int blocks = (n_seg + SEGS_PER_BLOCK - 1) / SEGS_PER_BLOCK;
    agg_seg_mean_kernel<<<blocks, THREADS>>>(vals, gidx, segs, out, E, n_seg);
}

// round 13
// speedup vs baseline: 1.7270x; 1.2497x over previous
#include <cuda_runtime.h>
#include <cuda_bf16.h>
#include <cstdint>

// AggregationLayer: y[s] = mean over edges e with segment_ids[e]==s of
//                   layer_values[gather_idx[e], :]
// d_in[0]: layer_values f32 [N_SRC*64]
// d_in[1]: gather_idx   i32 [E]
// d_in[2]: segment_ids  i32 [E] (sorted ascending)
// out: f32 [n_seg*64]

#define D 64
#define SEGS_PER_BLOCK 32
#define SEGS_PER_WARP 4
#define IDX_CAP 2048

// CSR row offsets scratch (n_seg <= 1M supported). +1 terminator.
__device__ int g_begin[1048577];

// Boundary finder: 4 edges per thread via int4; prev comes from the
// neighbor lane via shfl (only lane 0 re-loads), halving segs traffic.
__global__ void __launch_bounds__(256)
build_csr_kernel(const int* __restrict__ segs, int E, int n_seg)
{
    const int e4 = (blockIdx.x * blockDim.x + threadIdx.x) * 4;

    int s0 = 0, s1 = 0, s2 = 0, s3 = 0;
    const int rem = (e4 < E) ? (E - e4) : 0;
    if (rem >= 4) {
        int4 v = *reinterpret_cast<const int4*>(segs + e4);
        s0 = v.x; s1 = v.y; s2 = v.z; s3 = v.w;
    } else if (rem > 0) {
        s0 = __ldg(segs + e4);
        s1 = (rem > 1) ? __ldg(segs + e4 + 1) : s0;
        s2 = (rem > 2) ? __ldg(segs + e4 + 2) : s1;
        s3 = s2;
    }

    // prev = segs[e4-1]: last element of the neighbor lane's chunk
    int prev = __shfl_up_sync(0xffffffffu, s3, 1);
    const int lane = threadIdx.x & 31;
    if (lane == 0) {
        prev = (e4 == 0) ? -1 : ((e4 <= E) ? __ldg(segs + e4 - 1) : 0);
    }
    if (rem == 0) return;

    int cur[4] = {s0, s1, s2, s3};
    const int kmax = (rem < 4) ? rem : 4;
    #pragma unroll
    for (int k = 0; k < 4; ++k) {
        if (k < kmax) {
            for (int t = prev + 1; t <= cur[k]; ++t) g_begin[t] = e4 + k;
            prev = cur[k];
        }
    }
    if (e4 + kmax >= E) {
        for (int t = prev + 1; t <= n_seg; ++t) g_begin[t] = E;
    }
}

// Block handles 32 consecutive segments (4 per warp). One coalesced smem
// staging of offsets + the block's full edge-index span. Row-load phase uses
// predicated full-width 8-bursts: no serialized remainder loads.
__global__ void __launch_bounds__(256)
agg_seg_mean_kernel(const float* __restrict__ vals,
                    const int*   __restrict__ gidx,
                    float*       __restrict__ out,
                    int n_seg)
{
    __shared__ int s_begin[SEGS_PER_BLOCK + 1];
    __shared__ int s_idx[IDX_CAP];

    const int tid = threadIdx.x;
    const int b0  = blockIdx.x * SEGS_PER_BLOCK;

    if (tid <= SEGS_PER_BLOCK) {
        int s = b0 + tid;
        if (s > n_seg) s = n_seg;
        s_begin[tid] = g_begin[s];
    }
    __syncthreads();

    const int base0 = s_begin[0];
    const int span  = s_begin[SEGS_PER_BLOCK] - base0;
    const bool cached = (span <= IDX_CAP);

    if (cached) {
        for (int i = tid; i < span; i += 256)
            s_idx[i] = __ldcs(gidx + base0 + i);   // streaming: keep L2 for table
    }
    __syncthreads();

    const int w    = tid >> 5;
    const int lane = tid & 31;

    const float2* __restrict__ vals2 = reinterpret_cast<const float2*>(vals);

    #pragma unroll
    for (int ss = 0; ss < SEGS_PER_WARP; ++ss) {
        const int sl = w * SEGS_PER_WARP + ss;   // local segment index
        const int s  = b0 + sl;
        if (s >= n_seg) break;

        const int begin = s_begin[sl];
        const int end   = s_begin[sl + 1];
        const int cnt   = end - begin;

        float ax = 0.f, ay = 0.f;

        if (cached) {
            const int j0   = begin - base0;
            const int jend = end - base0;
            // predicated full-width bursts: every iteration issues 8
            // independent loads; out-of-range slots re-load edge j0
            // (L1 hit) with weight 0.
            for (int j = j0; j < jend; j += 8) {
                #pragma unroll
                for (int k = 0; k < 8; ++k) {
                    const int  jj = j + k;
                    const bool ok = (jj < jend);
                    const int  r  = s_idx[ok ? jj : j0];
                    const float w8 = ok ? 1.0f : 0.0f;
                    float2 v = __ldg(vals2 + (size_t)r * (D/2) + lane);
                    ax = fmaf(w8, v.x, ax);
                    ay = fmaf(w8, v.y, ay);
                }
            }
        } else {
            // rare fallback: block's edge span exceeded the smem cache
            for (int e = begin; e < end; e += 8) {
                #pragma unroll
                for (int k = 0; k < 8; ++k) {
                    const int  ee = e + k;
                    const bool ok = (ee < end);
                    const int  r  = __ldg(gidx + (ok ? ee : begin));
                    const float w8 = ok ? 1.0f : 0.0f;
                    float2 v = __ldg(vals2 + (size_t)r * (D/2) + lane);
                    ax = fmaf(w8, v.x, ax);
                    ay = fmaf(w8, v.y, ay);
                }
            }
        }

        const float inv = 1.0f / (float)max(cnt, 1);
        float2 res;
        res.x = ax * inv;
        res.y = ay * inv;
        // streaming store: output never re-read; keep L2 for the table
        __stcs(reinterpret_cast<float2*>(out) + (size_t)s * (D/2) + lane, res);
    }
}

extern "C" void kernel_launch(void* const* d_in, const int* in_sizes, int n_in,
                              void* d_out, int out_size)
{
    const float* vals = (const float*)d_in[0];
    const int*   gidx = (const int*)d_in[1];
    const int*   segs = (const int*)d_in[2];
    float*       out  = (float*)d_out;

    const int E     = in_sizes[1];
    const int n_seg = out_size / D;

    // 1) build CSR offsets (4 edges/thread, single-pass read)
    {
        const int threads = 256;
        const int elems_per_block = threads * 4;
        const int blocks = (E + elems_per_block - 1) / elems_per_block;
        build_csr_kernel<<<blocks, threads>>>(segs, E, n_seg);
    }
    // 2) block-staged (32 segs) warp-per-segment gather + mean
    {
        const int threads = 256;
        const int blocks = (n_seg + SEGS_PER_BLOCK - 1) / SEGS_PER_BLOCK;
        agg_seg_mean_kernel<<<blocks, threads>>>(vals, gidx, out, n_seg);
    }
}